// round 1
// baseline (speedup 1.0000x reference)
#include <cuda_runtime.h>

#define NANCH 2048
#define NCLS 21
#define MAXOUT 200
#define NMS_THR 0.5f
#define SCORE_THR 0.5f
#define CAND_CAP (NCLS * MAXOUT)   /* 4200 */
#define SORT_N 8192

// Scratch (no allocations allowed): decoded boxes in sorted order per class,
// per-class candidate keys (rank-ordered), per-class counts, per-class best.
__device__ float g_boxes[NCLS * NANCH * 4];
__device__ unsigned long long g_cand[NCLS * MAXOUT];
__device__ int g_cnt[NCLS];
__device__ unsigned long long g_best[NCLS];

// ---------------------------------------------------------------------------
// Kernel 1: one block per class. Score + stable sort + decode + greedy NMS
// with early termination at the 200th kept box + candidate emission.
// ---------------------------------------------------------------------------
__global__ __launch_bounds__(1024, 1)
void class_nms_kernel(const float* __restrict__ rois,
                      const float* __restrict__ deltas,
                      const float* __restrict__ probs)
{
    const int c = blockIdx.x;
    const int t = threadIdx.x;

    // 32KB reusable region: keys (16KB) -> boxes SoA (32KB) -> scan buffers
    __shared__ __align__(16) unsigned char sraw[32768];
    __shared__ unsigned char keep[NANCH];

    unsigned long long* skey = (unsigned long long*)sraw;

    // ---- phase 0: per-anchor argmax mask + score, pack sort keys ----------
    // key = score_bits (desc) | (2047 - n)  -> desc sort == stable argsort(-s)
    #pragma unroll
    for (int rep = 0; rep < 2; rep++) {
        int n = t + rep * 1024;
        const float* pr = probs + n * NCLS;
        float best = pr[0];
        int am = 0;
        #pragma unroll
        for (int k = 1; k < NCLS; k++) {
            float v = pr[k];
            if (v > best) { best = v; am = k; }
        }
        float sc = (am != 0) ? pr[c] : 0.0f;
        skey[n] = ((unsigned long long)__float_as_uint(sc) << 32)
                  | (unsigned)(NANCH - 1 - n);
    }
    __syncthreads();

    // ---- phase 1: bitonic sort, descending, 2048 keys, 1024 threads -------
    for (int k = 2; k <= NANCH; k <<= 1) {
        for (int j = k >> 1; j > 0; j >>= 1) {
            int idx = ((t & ~(j - 1)) << 1) | (t & (j - 1));
            int pid = idx | j;
            unsigned long long a = skey[idx];
            unsigned long long b = skey[pid];
            bool descBlock = ((idx & k) == 0);
            if ((a < b) == descBlock) { skey[idx] = b; skey[pid] = a; }
            __syncthreads();
        }
    }

    // grab my two sorted keys into registers, then reuse smem for boxes
    unsigned long long k0 = skey[t];
    unsigned long long k1 = skey[t + 1024];
    __syncthreads();

    float* by1 = (float*)(sraw);
    float* bx1 = (float*)(sraw + 8192);
    float* by2 = (float*)(sraw + 16384);
    float* bx2 = (float*)(sraw + 24576);

    float sc0 = 0.0f, sc1 = 0.0f;

    // ---- phase 2: decode boxes in sorted order ----------------------------
    #pragma unroll
    for (int rep = 0; rep < 2; rep++) {
        int p = t + rep * 1024;
        unsigned long long key = rep ? k1 : k0;
        int n = NANCH - 1 - (int)(key & 0xFFFFFFFFu);
        float y1 = rois[n * 4 + 0];
        float x1 = rois[n * 4 + 1];
        float y2 = rois[n * 4 + 2];
        float x2 = rois[n * 4 + 3];
        const float* dd = deltas + n * (NCLS * 4) + c * 4;
        float dy = dd[0] * 0.1f;
        float dx = dd[1] * 0.1f;
        float dh = dd[2] * 0.2f;
        float dw = dd[3] * 0.2f;
        float h  = y2 - y1;
        float w  = x2 - x1;
        float cy = y1 + 0.5f * h;
        float cx = x1 + 0.5f * w;
        float nh = expf(dh) * h;
        float nw = expf(dw) * w;
        float ncy = dy * h + cy;
        float ncx = dx * w + cx;
        float oy1 = ncy - 0.5f * nh;
        float ox1 = ncx - 0.5f * nw;
        float oy2 = ncy + 0.5f * nh;
        float ox2 = ncx + 0.5f * nw;
        by1[p] = oy1; bx1[p] = ox1; by2[p] = oy2; bx2[p] = ox2;
        float* gb = g_boxes + (c * NANCH + p) * 4;
        gb[0] = oy1; gb[1] = ox1; gb[2] = oy2; gb[3] = ox2;
        keep[p] = 1;
        float s = __uint_as_float((unsigned)(key >> 32));
        if (rep) sc1 = s; else sc0 = s;
    }
    __syncthreads();

    // ---- phase 3: greedy NMS with early stop at 200th kept ----------------
    // keep[i] reads are uniform; barrier only on iterations that wrote.
    int cnt = 0;
    int i_stop = NANCH - 1;
    for (int i = 0; i < NANCH; i++) {
        if (keep[i]) {
            cnt++;
            if (cnt >= MAXOUT) { i_stop = i; break; }  // 200th kept: done
            float y1i = by1[i], x1i = bx1[i], y2i = by2[i], x2i = bx2[i];
            float ai = (y2i - y1i) * (x2i - x1i);
            for (int j = i + 1 + t; j < NANCH; j += 1024) {
                if (!keep[j]) continue;
                float jy1 = by1[j], jx1 = bx1[j], jy2 = by2[j], jx2 = bx2[j];
                float ih = fminf(y2i, jy2) - fmaxf(y1i, jy1);
                float iw = fminf(x2i, jx2) - fmaxf(x1i, jx1);
                ih = fmaxf(ih, 0.0f);
                iw = fmaxf(iw, 0.0f);
                float inter = ih * iw;
                float aj = (jy2 - jy1) * (jx2 - jx1);
                float iou = inter / (ai + aj - inter + 1e-9f);
                if (iou > NMS_THR) keep[j] = 0;
            }
            __syncthreads();
        }
    }
    __syncthreads();

    // ---- phase 4: rank candidates (prefix scan) and emit ------------------
    int f0 = (keep[t] && t <= i_stop && sc0 > SCORE_THR) ? 1 : 0;
    int f1 = (keep[t + 1024] && (t + 1024) <= i_stop && sc1 > SCORE_THR) ? 1 : 0;

    int* A = (int*)(sraw);
    int* B = (int*)(sraw + 8192);
    A[t] = f0;
    A[t + 1024] = f1;
    __syncthreads();
    int* src = A;
    int* dst = B;
    for (int off = 1; off < NANCH; off <<= 1) {
        int v0 = src[t] + ((t >= off) ? src[t - off] : 0);
        int p1 = t + 1024;
        int v1 = src[p1] + ((p1 >= off) ? src[p1 - off] : 0);
        dst[t] = v0;
        dst[p1] = v1;
        __syncthreads();
        int* tmp = src; src = dst; dst = tmp;
    }

    if (f0) {
        int rank = src[t] - 1;
        g_cand[c * MAXOUT + rank] =
            ((k0 >> 32) << 32) | (unsigned)(0xFFFFFFFFu - (unsigned)(c * NANCH + t));
    }
    if (f1) {
        int rank = src[t + 1024] - 1;
        g_cand[c * MAXOUT + rank] =
            ((k1 >> 32) << 32) | (unsigned)(0xFFFFFFFFu - (unsigned)(c * NANCH + t + 1024));
    }
    if (t == 0) {
        g_cnt[c] = src[NANCH - 1];
        // rank-0 is always kept: per-class fallback best
        g_best[c] = ((k0 >> 32) << 32)
                    | (unsigned)(0xFFFFFFFFu - (unsigned)(c * NANCH));
    }
}

// ---------------------------------------------------------------------------
// Kernel 2: global top-200 over <=4200 candidates via bitonic sort of 8192
// padded keys (64KB dynamic smem), plus fallback path.
// ---------------------------------------------------------------------------
__global__ __launch_bounds__(1024, 1)
void topk_kernel(float* __restrict__ out)
{
    extern __shared__ unsigned long long keys[];
    const int t = threadIdx.x;

    #pragma unroll
    for (int rep = 0; rep < SORT_N / 1024; rep++) {
        int idx = t + rep * 1024;
        unsigned long long key = 0ULL;
        if (idx < CAND_CAP) {
            int c = idx / MAXOUT;
            int r = idx - c * MAXOUT;
            if (r < g_cnt[c]) key = g_cand[idx];
        }
        keys[idx] = key;
    }
    __syncthreads();

    for (int k = 2; k <= SORT_N; k <<= 1) {
        for (int j = k >> 1; j > 0; j >>= 1) {
            #pragma unroll
            for (int rep = 0; rep < SORT_N / 2048; rep++) {
                int q = t + rep * 1024;
                int idx = ((q & ~(j - 1)) << 1) | (q & (j - 1));
                int pid = idx | j;
                unsigned long long a = keys[idx];
                unsigned long long b = keys[pid];
                bool descBlock = ((idx & k) == 0);
                if ((a < b) == descBlock) { keys[idx] = b; keys[pid] = a; }
            }
            __syncthreads();
        }
    }

    bool fb = (keys[0] == 0ULL);  // no candidate passed threshold -> fallback

    if (t < MAXOUT) {
        float b0 = 0.f, b1 = 0.f, b2 = 0.f, b3 = 0.f, lab = 0.f, sc = 0.f;
        if (!fb) {
            unsigned long long key = keys[t];
            if (key != 0ULL) {
                sc = __uint_as_float((unsigned)(key >> 32));
                unsigned flat = 0xFFFFFFFFu - (unsigned)(key & 0xFFFFFFFFu);
                lab = (float)(flat / NANCH);
                const float* gb = g_boxes + flat * 4;
                b0 = fminf(fmaxf(gb[0], 0.f), 1.f);
                b1 = fminf(fmaxf(gb[1], 0.f), 1.f);
                b2 = fminf(fmaxf(gb[2], 0.f), 1.f);
                b3 = fminf(fmaxf(gb[3], 0.f), 1.f);
            }
        } else if (t == 0) {
            unsigned long long best = 0ULL;
            #pragma unroll
            for (int c = 0; c < NCLS; c++) {
                unsigned long long v = g_best[c];
                if (v > best) best = v;
            }
            float s = __uint_as_float((unsigned)(best >> 32));
            if (s >= 0.001f) {
                sc = s;
                unsigned flat = 0xFFFFFFFFu - (unsigned)(best & 0xFFFFFFFFu);
                lab = (float)(flat / NANCH);
                const float* gb = g_boxes + flat * 4;
                b0 = fminf(fmaxf(gb[0], 0.f), 1.f);
                b1 = fminf(fmaxf(gb[1], 0.f), 1.f);
                b2 = fminf(fmaxf(gb[2], 0.f), 1.f);
                b3 = fminf(fmaxf(gb[3], 0.f), 1.f);
            }
        }
        // output layout: boxes (1,200,4) | labels (1,200) | scores (1,200)
        out[t * 4 + 0] = b0;
        out[t * 4 + 1] = b1;
        out[t * 4 + 2] = b2;
        out[t * 4 + 3] = b3;
        out[MAXOUT * 4 + t] = lab;
        out[MAXOUT * 5 + t] = sc;
    }
}

extern "C" void kernel_launch(void* const* d_in, const int* in_sizes, int n_in,
                              void* d_out, int out_size)
{
    (void)in_sizes; (void)n_in; (void)out_size;
    const float* rois   = (const float*)d_in[0];
    const float* deltas = (const float*)d_in[1];
    const float* probs  = (const float*)d_in[2];
    float* out = (float*)d_out;

    cudaFuncSetAttribute(topk_kernel,
                         cudaFuncAttributeMaxDynamicSharedMemorySize,
                         SORT_N * (int)sizeof(unsigned long long));

    class_nms_kernel<<<NCLS, 1024>>>(rois, deltas, probs);
    topk_kernel<<<1, 1024, SORT_N * sizeof(unsigned long long)>>>(out);
}

// round 2
// speedup vs baseline: 1.3358x; 1.3358x over previous
#include <cuda_runtime.h>

#define NANCH 2048
#define NCLS 21
#define MAXOUT 200
#define NMS_THR 0.5f
#define SCORE_THR 0.5f
#define CAND_CAP (NCLS * MAXOUT)   /* 4200 */
#define KCAP 4224
#define FULLMASK 0xFFFFFFFFu

typedef unsigned long long ull;

// Scratch (no allocations allowed)
__device__ ull   g_cand[CAND_CAP];          // per-class rank-ordered candidate keys
__device__ float g_cand_box[CAND_CAP * 4];  // matching boxes
__device__ int   g_cnt[NCLS];
__device__ ull   g_best[NCLS];              // per-class fallback (rank-0 kept)
__device__ float g_best_box[NCLS * 4];

__device__ __forceinline__ ull cmpx(ull v, ull o, bool takeMax) {
    return takeMax ? (v > o ? v : o) : (v < o ? v : o);
}

// Register bitonic tail: stages j=32 (lo<->hi in-thread) then j=16..1 (shfl_xor).
__device__ __forceinline__ void reg_tail(ull& lo, ull& hi, int e_lo, int k, int lane) {
    // j = 32 (only valid when k >= 64)
    if (k >= 64) {
        bool desc = ((e_lo & k) == 0);
        if ((lo < hi) == desc) { ull tmp = lo; lo = hi; hi = tmp; }
    }
    #pragma unroll
    for (int j = 16; j >= 1; j >>= 1) {
        if (j > (k >> 1)) continue;
        bool is_low = ((lane & j) == 0);
        {
            ull o = __shfl_xor_sync(FULLMASK, lo, j);
            bool desc = ((e_lo & k) == 0);
            lo = cmpx(lo, o, is_low == desc);
        }
        {
            ull o = __shfl_xor_sync(FULLMASK, hi, j);
            bool desc = (((e_lo + 32) & k) == 0);
            hi = cmpx(hi, o, is_low == desc);
        }
    }
}

// ---------------------------------------------------------------------------
// Kernel 1: one block per class.
// ---------------------------------------------------------------------------
__global__ __launch_bounds__(1024, 1)
void class_nms_kernel(const float* __restrict__ rois,
                      const float* __restrict__ deltas,
                      const float* __restrict__ probs)
{
    __shared__ __align__(16) unsigned char sraw[35360];
    float* by1 = (float*)(sraw);
    float* bx1 = (float*)(sraw + 8192);
    float* by2 = (float*)(sraw + 16384);
    float* bx2 = (float*)(sraw + 24576);
    ull*   skey = (ull*)(sraw);                    // overlaps boxes (freed before decode)
    unsigned char* keep = sraw + 32768;            // 2048 B
    unsigned* ballots = (unsigned*)(sraw + 34816); // 64 * 4
    int* wpre = (int*)(sraw + 35072);              // 64 * 4
    int* s_cnt  = (int*)(sraw + 35328);
    int* s_stop = (int*)(sraw + 35332);
    unsigned* s_mask = (unsigned*)(sraw + 35336);

    const int c = blockIdx.x;
    const int t = threadIdx.x;
    const int lane = t & 31;
    const int warp = t >> 5;
    const int e_lo = warp * 64 + lane;   // register-sort element mapping
    const int e_hi = e_lo + 32;

    // ---- phase 0: scores -> keys directly in registers ---------------------
    ull lo, hi;
    {
        const float* pr = probs + e_lo * NCLS;
        float p0 = pr[0];
        float m = pr[1];
        #pragma unroll
        for (int k2 = 2; k2 < NCLS; k2++) m = fmaxf(m, pr[k2]);
        float sc = (m > p0) ? pr[c] : 0.0f;
        lo = ((ull)__float_as_uint(sc) << 32) | (unsigned)(NANCH - 1 - e_lo);
    }
    {
        const float* pr = probs + e_hi * NCLS;
        float p0 = pr[0];
        float m = pr[1];
        #pragma unroll
        for (int k2 = 2; k2 < NCLS; k2++) m = fmaxf(m, pr[k2]);
        float sc = (m > p0) ? pr[c] : 0.0f;
        hi = ((ull)__float_as_uint(sc) << 32) | (unsigned)(NANCH - 1 - e_hi);
    }

    // ---- phase 1: hybrid bitonic sort (descending) --------------------------
    // k = 2..64 fully in registers (no barriers)
    #pragma unroll
    for (int k = 2; k <= 64; k <<= 1)
        reg_tail(lo, hi, e_lo, k, lane);
    skey[e_lo] = lo; skey[e_hi] = hi;
    __syncthreads();

    for (int k = 128; k <= NANCH; k <<= 1) {
        for (int j = k >> 1; j >= 64; j >>= 1) {
            int idx = ((t & ~(j - 1)) << 1) | (t & (j - 1));
            int pid = idx | j;
            ull a = skey[idx];
            ull b = skey[pid];
            bool desc = ((idx & k) == 0);
            if ((a < b) == desc) { skey[idx] = b; skey[pid] = a; }
            __syncthreads();
        }
        lo = skey[e_lo]; hi = skey[e_hi];
        reg_tail(lo, hi, e_lo, k, lane);
        skey[e_lo] = lo; skey[e_hi] = hi;
        __syncthreads();
    }

    // grab my two sorted keys, then boxes overwrite the key region
    ull k0 = skey[t];
    ull k1 = skey[t + 1024];
    __syncthreads();

    float sc0 = __uint_as_float((unsigned)(k0 >> 32));
    float sc1 = __uint_as_float((unsigned)(k1 >> 32));

    // ---- phase 2: decode boxes in sorted order ------------------------------
    #pragma unroll
    for (int rep = 0; rep < 2; rep++) {
        int p = t + rep * 1024;
        ull key = rep ? k1 : k0;
        int n = NANCH - 1 - (int)(key & 0xFFFFFFFFu);
        float4 r = ((const float4*)rois)[n];
        float4 d = *(const float4*)(deltas + n * (NCLS * 4) + c * 4);
        float dy = d.x * 0.1f, dx = d.y * 0.1f, dh = d.z * 0.2f, dw = d.w * 0.2f;
        float h  = r.z - r.x;
        float w  = r.w - r.y;
        float cy = r.x + 0.5f * h;
        float cx = r.y + 0.5f * w;
        float nh = expf(dh) * h;
        float nw = expf(dw) * w;
        float ncy = dy * h + cy;
        float ncx = dx * w + cx;
        by1[p] = ncy - 0.5f * nh;
        bx1[p] = ncx - 0.5f * nw;
        by2[p] = ncy + 0.5f * nh;
        bx2[p] = ncx + 0.5f * nw;
        keep[p] = 1;
    }
    __syncthreads();

    // ---- phase 3: chunked greedy NMS (exact), early stop at 200th kept ------
    int cnt = 0;
    int i_stop = NANCH - 1;
    for (int cs = 0; cs < NANCH; cs += 32) {
        if (warp == 0) {
            int e = cs + lane;
            float y1 = by1[e], x1 = bx1[e], y2 = by2[e], x2 = bx2[e];
            float area = (y2 - y1) * (x2 - x1);
            unsigned alive = __ballot_sync(FULLMASK, keep[e] != 0);
            unsigned rem = alive;
            while (rem) {
                int i = __ffs(rem) - 1;
                rem &= rem - 1;
                float iy1 = __shfl_sync(FULLMASK, y1, i);
                float ix1 = __shfl_sync(FULLMASK, x1, i);
                float iy2 = __shfl_sync(FULLMASK, y2, i);
                float ix2 = __shfl_sync(FULLMASK, x2, i);
                float ia  = __shfl_sync(FULLMASK, area, i);
                bool sup = false;
                if (lane > i && ((alive >> lane) & 1)) {
                    float ih = fmaxf(fminf(iy2, y2) - fmaxf(iy1, y1), 0.0f);
                    float iw = fmaxf(fminf(ix2, x2) - fmaxf(ix1, x1), 0.0f);
                    float inter = ih * iw;
                    float iou = inter / (ia + area - inter + 1e-9f);
                    sup = iou > NMS_THR;
                }
                unsigned supm = __ballot_sync(FULLMASK, sup);
                alive &= ~supm;
                rem &= ~supm;
            }
            keep[e] = (alive >> lane) & 1;
            if (lane == 0) {
                int kic = __popc(alive);
                if (cnt + kic >= MAXOUT) {
                    int need = MAXOUT - cnt;
                    unsigned m = alive;
                    int bit = 0;
                    for (int q = 0; q < need; q++) { bit = __ffs(m) - 1; m &= m - 1; }
                    *s_stop = cs + bit;
                    *s_cnt = MAXOUT;
                } else {
                    *s_stop = -1;
                    *s_cnt = cnt + kic;
                }
                *s_mask = alive;
            }
        }
        __syncthreads();
        cnt = *s_cnt;
        int st = *s_stop;
        unsigned mask = *s_mask;
        if (st >= 0) { i_stop = st; break; }
        // suppress all later boxes against this chunk's kept set
        for (int j = cs + 32 + t; j < NANCH; j += 1024) {
            if (!keep[j]) continue;
            float jy1 = by1[j], jx1 = bx1[j], jy2 = by2[j], jx2 = bx2[j];
            float aj = (jy2 - jy1) * (jx2 - jx1);
            unsigned m = mask;
            bool dead = false;
            while (m) {
                int i = __ffs(m) - 1; m &= m - 1;
                int e = cs + i;
                float ey1 = by1[e], ex1 = bx1[e], ey2 = by2[e], ex2 = bx2[e];
                float ih = fmaxf(fminf(ey2, jy2) - fmaxf(ey1, jy1), 0.0f);
                float iw = fmaxf(fminf(ex2, jx2) - fmaxf(ex1, jx1), 0.0f);
                float inter = ih * iw;
                float ai = (ey2 - ey1) * (ex2 - ex1);
                float iou = inter / (ai + aj - inter + 1e-9f);
                if (iou > NMS_THR) { dead = true; break; }
            }
            if (dead) keep[j] = 0;
        }
        __syncthreads();
    }
    __syncthreads();

    // ---- phase 4: ballot-scan ranking + candidate emission -------------------
    bool f0 = keep[t] && (t <= i_stop) && (sc0 > SCORE_THR);
    bool f1 = keep[t + 1024] && ((t + 1024) <= i_stop) && (sc1 > SCORE_THR);
    unsigned b0 = __ballot_sync(FULLMASK, f0);
    unsigned b1 = __ballot_sync(FULLMASK, f1);
    if (lane == 0) { ballots[warp] = b0; ballots[32 + warp] = b1; }
    __syncthreads();
    if (t < 64) {
        int s = 0;
        for (int u = 0; u < t; u++) s += __popc(ballots[u]);
        wpre[t] = s;
    }
    __syncthreads();

    unsigned lmask = (1u << lane) - 1u;
    if (f0) {
        int rank = wpre[warp] + __popc(b0 & lmask);
        int flatc = c * MAXOUT + rank;
        g_cand[flatc] = ((k0 >> 32) << 32) | (unsigned)(0xFFFFFFFFu - (unsigned)flatc);
        ((float4*)g_cand_box)[flatc] = make_float4(by1[t], bx1[t], by2[t], bx2[t]);
    }
    if (f1) {
        int rank = wpre[32 + warp] + __popc(b1 & lmask);
        int flatc = c * MAXOUT + rank;
        g_cand[flatc] = ((k1 >> 32) << 32) | (unsigned)(0xFFFFFFFFu - (unsigned)flatc);
        int p = t + 1024;
        ((float4*)g_cand_box)[flatc] = make_float4(by1[p], bx1[p], by2[p], bx2[p]);
    }
    if (t == 0) {
        int total = 0;
        #pragma unroll
        for (int u = 0; u < 64; u++) total += __popc(ballots[u]);
        g_cnt[c] = total;
        // rank-0 is always kept: per-class fallback (key comparable across classes)
        g_best[c] = ((k0 >> 32) << 32) | (unsigned)(0xFFFFFFFFu - (unsigned)c);
        ((float4*)g_best_box)[c] = make_float4(by1[0], bx1[0], by2[0], bx2[0]);
    }
}

// ---------------------------------------------------------------------------
// Kernel 2: global top-200 via histogram select + exact ranking of boundary set
// ---------------------------------------------------------------------------
__global__ __launch_bounds__(1024, 1)
void topk_kernel(float* __restrict__ out)
{
    __shared__ ull keys[KCAP];
    __shared__ unsigned short subset[KCAP];
    __shared__ ull slots[MAXOUT];
    __shared__ int hist[257];
    __shared__ int s_misc[2];     // [0]=subset count, [1]=bstar
    __shared__ int scnt_s[NCLS];

    const int t = threadIdx.x;

    if (t < 257) hist[t] = 0;
    if (t < MAXOUT) slots[t] = 0ULL;
    if (t < NCLS) scnt_s[t] = g_cnt[t];
    if (t == 0) s_misc[0] = 0;
    __syncthreads();

    // load valid keys + histogram on score bits
    #pragma unroll
    for (int rep = 0; rep < 5; rep++) {
        int i = t + rep * 1024;
        if (i >= KCAP) break;
        ull key = 0ULL;
        if (i < CAND_CAP) {
            int c = i / MAXOUT;
            int r = i - c * MAXOUT;
            if (r < scnt_s[c]) key = g_cand[i];
        }
        keys[i] = key;
        if (key) {
            unsigned sb = (unsigned)(key >> 32);
            int bin = (int)((sb - 0x3F000000u) >> 15);
            bin = min(max(bin, 0), 255);
            atomicAdd(&hist[bin], 1);
        }
    }
    __syncthreads();

    if (t == 0) {
        int suf = 0, bstar = 0;
        for (int b = 255; b >= 0; b--) {
            suf += hist[b];
            if (suf >= MAXOUT) { bstar = b; break; }
        }
        s_misc[1] = bstar;
    }
    __syncthreads();
    int bstar = s_misc[1];

    // compact boundary superset (everything outside is strictly smaller)
    #pragma unroll
    for (int rep = 0; rep < 5; rep++) {
        int i = t + rep * 1024;
        if (i >= KCAP) break;
        ull key = keys[i];
        if (key) {
            unsigned sb = (unsigned)(key >> 32);
            int bin = (int)((sb - 0x3F000000u) >> 15);
            bin = min(max(bin, 0), 255);
            if (bin >= bstar) {
                int pos = atomicAdd(&s_misc[0], 1);
                subset[pos] = (unsigned short)i;
            }
        }
    }
    __syncthreads();
    int M = s_misc[0];

    // exact rank within subset (keys unique -> unique ranks)
    for (int s = t; s < M; s += 1024) {
        ull k = keys[subset[s]];
        int r = 0;
        for (int m = 0; m < M; m++)
            r += (keys[subset[m]] > k) ? 1 : 0;
        if (r < MAXOUT) slots[r] = k;
    }
    __syncthreads();

    if (t < MAXOUT) {
        float b0 = 0.f, b1 = 0.f, b2 = 0.f, b3 = 0.f, lab = 0.f, sc = 0.f;
        ull key = slots[t];
        if (key != 0ULL) {
            sc = __uint_as_float((unsigned)(key >> 32));
            unsigned flatc = 0xFFFFFFFFu - (unsigned)(key & 0xFFFFFFFFu);
            lab = (float)(flatc / MAXOUT);
            float4 bb = ((const float4*)g_cand_box)[flatc];
            b0 = fminf(fmaxf(bb.x, 0.f), 1.f);
            b1 = fminf(fmaxf(bb.y, 0.f), 1.f);
            b2 = fminf(fmaxf(bb.z, 0.f), 1.f);
            b3 = fminf(fmaxf(bb.w, 0.f), 1.f);
        } else if (t == 0 && M == 0) {
            // fallback: best kept box overall (per-class rank-0 maxima)
            ull best = 0ULL;
            #pragma unroll
            for (int c2 = 0; c2 < NCLS; c2++) {
                ull v = g_best[c2];
                if (v > best) best = v;
            }
            float s = __uint_as_float((unsigned)(best >> 32));
            if (s >= 0.001f) {
                sc = s;
                int c2 = (int)(0xFFFFFFFFu - (unsigned)(best & 0xFFFFFFFFu));
                lab = (float)c2;
                float4 bb = ((const float4*)g_best_box)[c2];
                b0 = fminf(fmaxf(bb.x, 0.f), 1.f);
                b1 = fminf(fmaxf(bb.y, 0.f), 1.f);
                b2 = fminf(fmaxf(bb.z, 0.f), 1.f);
                b3 = fminf(fmaxf(bb.w, 0.f), 1.f);
            }
        }
        out[t * 4 + 0] = b0;
        out[t * 4 + 1] = b1;
        out[t * 4 + 2] = b2;
        out[t * 4 + 3] = b3;
        out[MAXOUT * 4 + t] = lab;
        out[MAXOUT * 5 + t] = sc;
    }
}

extern "C" void kernel_launch(void* const* d_in, const int* in_sizes, int n_in,
                              void* d_out, int out_size)
{
    (void)in_sizes; (void)n_in; (void)out_size;
    const float* rois   = (const float*)d_in[0];
    const float* deltas = (const float*)d_in[1];
    const float* probs  = (const float*)d_in[2];
    float* out = (float*)d_out;

    class_nms_kernel<<<NCLS, 1024>>>(rois, deltas, probs);
    topk_kernel<<<1, 1024>>>(out);
}

// round 3
// speedup vs baseline: 1.3400x; 1.0031x over previous
#include <cuda_runtime.h>

#define NANCH 2048
#define NCLS 21
#define MAXOUT 200
#define NMS_THR 0.5f
#define SCORE_THR 0.5f
#define CAND_CAP (NCLS * MAXOUT)   /* 4200 */
#define KCAP 4224
#define FULLMASK 0xFFFFFFFFu

typedef unsigned long long ull;

// Scratch (no allocations allowed)
__device__ float g_scoreT[NCLS * NANCH];    // transposed masked scores
__device__ ull   g_cand[CAND_CAP];          // per-class rank-ordered candidate keys
__device__ float g_cand_box[CAND_CAP * 4];  // matching boxes
__device__ int   g_cnt[NCLS];
__device__ ull   g_best[NCLS];              // per-class fallback (rank-0 kept)
__device__ float g_best_box[NCLS * 4];

// ---------------------------------------------------------------------------
// Kernel 0: per-anchor argmax mask + transposed score write (done ONCE).
// 8 blocks x 256 threads; each block stages 256 anchors' probs in smem.
// ---------------------------------------------------------------------------
__global__ __launch_bounds__(256)
void score_kernel(const float* __restrict__ probs)
{
    __shared__ float sp[256 * NCLS];
    const int t = threadIdx.x;
    const int base = blockIdx.x * 256;          // anchor base

    // coalesced stage-in of this block's 256x21 prob slab
    const float* src = probs + base * NCLS;
    #pragma unroll
    for (int i = t; i < 256 * NCLS; i += 256) sp[i] = src[i];
    __syncthreads();

    const float* pr = sp + t * NCLS;
    float p0 = pr[0];
    float m = pr[1];
    #pragma unroll
    for (int k = 2; k < NCLS; k++) m = fmaxf(m, pr[k]);
    bool valid = (m > p0);                      // argmax != 0

    int n = base + t;
    #pragma unroll
    for (int c = 0; c < NCLS; c++)              // coalesced per-c stores
        g_scoreT[c * NANCH + n] = valid ? pr[c] : 0.0f;
}

// no-op kernel: shifts ncu capture parity so class_nms_kernel gets profiled
__global__ void nop_kernel() {}

__device__ __forceinline__ ull cmpx(ull v, ull o, bool takeMax) {
    return takeMax ? (v > o ? v : o) : (v < o ? v : o);
}

// Register bitonic tail: stages j=32 (lo<->hi in-thread) then j=16..1 (shfl_xor).
__device__ __forceinline__ void reg_tail(ull& lo, ull& hi, int e_lo, int k, int lane) {
    if (k >= 64) {
        bool desc = ((e_lo & k) == 0);
        if ((lo < hi) == desc) { ull tmp = lo; lo = hi; hi = tmp; }
    }
    #pragma unroll
    for (int j = 16; j >= 1; j >>= 1) {
        if (j > (k >> 1)) continue;
        bool is_low = ((lane & j) == 0);
        {
            ull o = __shfl_xor_sync(FULLMASK, lo, j);
            bool desc = ((e_lo & k) == 0);
            lo = cmpx(lo, o, is_low == desc);
        }
        {
            ull o = __shfl_xor_sync(FULLMASK, hi, j);
            bool desc = (((e_lo + 32) & k) == 0);
            hi = cmpx(hi, o, is_low == desc);
        }
    }
}

// ---------------------------------------------------------------------------
// Kernel 1: one block per class.
// ---------------------------------------------------------------------------
__global__ __launch_bounds__(1024, 1)
void class_nms_kernel(const float* __restrict__ rois,
                      const float* __restrict__ deltas)
{
    __shared__ __align__(16) unsigned char sraw[35360];
    float* by1 = (float*)(sraw);
    float* bx1 = (float*)(sraw + 8192);
    float* by2 = (float*)(sraw + 16384);
    float* bx2 = (float*)(sraw + 24576);
    ull*   skey = (ull*)(sraw);                    // overlaps boxes (freed before decode)
    unsigned char* keep = sraw + 32768;            // 2048 B
    unsigned* ballots = (unsigned*)(sraw + 34816); // 64 * 4
    int* wpre = (int*)(sraw + 35072);              // 64 * 4
    int* s_cnt  = (int*)(sraw + 35328);
    int* s_stop = (int*)(sraw + 35332);
    unsigned* s_mask = (unsigned*)(sraw + 35336);

    const int c = blockIdx.x;
    const int t = threadIdx.x;
    const int lane = t & 31;
    const int warp = t >> 5;
    const int e_lo = warp * 64 + lane;   // register-sort element mapping
    const int e_hi = e_lo + 32;

    // ---- phase 0: coalesced score loads -> keys in registers ---------------
    const float* scT = g_scoreT + c * NANCH;
    float s_lo = scT[e_lo];
    float s_hi = scT[e_hi];
    ull lo = ((ull)__float_as_uint(s_lo) << 32) | (unsigned)(NANCH - 1 - e_lo);
    ull hi = ((ull)__float_as_uint(s_hi) << 32) | (unsigned)(NANCH - 1 - e_hi);

    // ---- phase 1: hybrid bitonic sort (descending) --------------------------
    #pragma unroll
    for (int k = 2; k <= 64; k <<= 1)
        reg_tail(lo, hi, e_lo, k, lane);
    skey[e_lo] = lo; skey[e_hi] = hi;
    __syncthreads();

    for (int k = 128; k <= NANCH; k <<= 1) {
        for (int j = k >> 1; j >= 64; j >>= 1) {
            int idx = ((t & ~(j - 1)) << 1) | (t & (j - 1));
            int pid = idx | j;
            ull a = skey[idx];
            ull b = skey[pid];
            bool desc = ((idx & k) == 0);
            if ((a < b) == desc) { skey[idx] = b; skey[pid] = a; }
            __syncthreads();
        }
        lo = skey[e_lo]; hi = skey[e_hi];
        reg_tail(lo, hi, e_lo, k, lane);
        skey[e_lo] = lo; skey[e_hi] = hi;
        __syncthreads();
    }

    // grab my two sorted keys, then boxes overwrite the key region
    ull k0 = skey[t];
    ull k1 = skey[t + 1024];
    __syncthreads();

    float sc0 = __uint_as_float((unsigned)(k0 >> 32));
    float sc1 = __uint_as_float((unsigned)(k1 >> 32));

    // ---- phase 2: decode boxes in sorted order ------------------------------
    #pragma unroll
    for (int rep = 0; rep < 2; rep++) {
        int p = t + rep * 1024;
        ull key = rep ? k1 : k0;
        int n = NANCH - 1 - (int)(key & 0xFFFFFFFFu);
        float4 r = ((const float4*)rois)[n];
        const float* dd = deltas + n * (NCLS * 4) + c * 4;  // 4B-aligned: scalar loads
        float dy = dd[0] * 0.1f;
        float dx = dd[1] * 0.1f;
        float dh = dd[2] * 0.2f;
        float dw = dd[3] * 0.2f;
        float h  = r.z - r.x;
        float w  = r.w - r.y;
        float cy = r.x + 0.5f * h;
        float cx = r.y + 0.5f * w;
        float nh = expf(dh) * h;
        float nw = expf(dw) * w;
        float ncy = dy * h + cy;
        float ncx = dx * w + cx;
        by1[p] = ncy - 0.5f * nh;
        bx1[p] = ncx - 0.5f * nw;
        by2[p] = ncy + 0.5f * nh;
        bx2[p] = ncx + 0.5f * nw;
        keep[p] = 1;
    }
    __syncthreads();

    // ---- phase 3: chunked greedy NMS (exact), early stop at 200th kept ------
    int cnt = 0;
    int i_stop = NANCH - 1;
    for (int cs = 0; cs < NANCH; cs += 32) {
        if (warp == 0) {
            int e = cs + lane;
            float y1 = by1[e], x1 = bx1[e], y2 = by2[e], x2 = bx2[e];
            float area = (y2 - y1) * (x2 - x1);
            unsigned alive = __ballot_sync(FULLMASK, keep[e] != 0);
            unsigned rem = alive;
            while (rem) {
                int i = __ffs(rem) - 1;
                rem &= rem - 1;
                float iy1 = __shfl_sync(FULLMASK, y1, i);
                float ix1 = __shfl_sync(FULLMASK, x1, i);
                float iy2 = __shfl_sync(FULLMASK, y2, i);
                float ix2 = __shfl_sync(FULLMASK, x2, i);
                float ia  = __shfl_sync(FULLMASK, area, i);
                bool sup = false;
                if (lane > i && ((alive >> lane) & 1)) {
                    float ih = fmaxf(fminf(iy2, y2) - fmaxf(iy1, y1), 0.0f);
                    float iw = fmaxf(fminf(ix2, x2) - fmaxf(ix1, x1), 0.0f);
                    float inter = ih * iw;
                    float iou = inter / (ia + area - inter + 1e-9f);
                    sup = iou > NMS_THR;
                }
                unsigned supm = __ballot_sync(FULLMASK, sup);
                alive &= ~supm;
                rem &= ~supm;
            }
            keep[e] = (alive >> lane) & 1;
            if (lane == 0) {
                int kic = __popc(alive);
                if (cnt + kic >= MAXOUT) {
                    int need = MAXOUT - cnt;
                    unsigned m = alive;
                    int bit = 0;
                    for (int q = 0; q < need; q++) { bit = __ffs(m) - 1; m &= m - 1; }
                    *s_stop = cs + bit;
                    *s_cnt = MAXOUT;
                } else {
                    *s_stop = -1;
                    *s_cnt = cnt + kic;
                }
                *s_mask = alive;
            }
        }
        __syncthreads();
        cnt = *s_cnt;
        int st = *s_stop;
        unsigned mask = *s_mask;
        if (st >= 0) { i_stop = st; break; }
        for (int j = cs + 32 + t; j < NANCH; j += 1024) {
            if (!keep[j]) continue;
            float jy1 = by1[j], jx1 = bx1[j], jy2 = by2[j], jx2 = bx2[j];
            float aj = (jy2 - jy1) * (jx2 - jx1);
            unsigned m = mask;
            bool dead = false;
            while (m) {
                int i = __ffs(m) - 1; m &= m - 1;
                int e = cs + i;
                float ey1 = by1[e], ex1 = bx1[e], ey2 = by2[e], ex2 = bx2[e];
                float ih = fmaxf(fminf(ey2, jy2) - fmaxf(ey1, jy1), 0.0f);
                float iw = fmaxf(fminf(ex2, jx2) - fmaxf(ex1, jx1), 0.0f);
                float inter = ih * iw;
                float ai = (ey2 - ey1) * (ex2 - ex1);
                float iou = inter / (ai + aj - inter + 1e-9f);
                if (iou > NMS_THR) { dead = true; break; }
            }
            if (dead) keep[j] = 0;
        }
        __syncthreads();
    }
    __syncthreads();

    // ---- phase 4: ballot-scan ranking + candidate emission -------------------
    bool f0 = keep[t] && (t <= i_stop) && (sc0 > SCORE_THR);
    bool f1 = keep[t + 1024] && ((t + 1024) <= i_stop) && (sc1 > SCORE_THR);
    unsigned b0 = __ballot_sync(FULLMASK, f0);
    unsigned b1 = __ballot_sync(FULLMASK, f1);
    if (lane == 0) { ballots[warp] = b0; ballots[32 + warp] = b1; }
    __syncthreads();
    if (t < 64) {
        int s = 0;
        for (int u = 0; u < t; u++) s += __popc(ballots[u]);
        wpre[t] = s;
    }
    __syncthreads();

    unsigned lmask = (1u << lane) - 1u;
    if (f0) {
        int rank = wpre[warp] + __popc(b0 & lmask);
        int flatc = c * MAXOUT + rank;
        g_cand[flatc] = ((k0 >> 32) << 32) | (unsigned)(0xFFFFFFFFu - (unsigned)flatc);
        ((float4*)g_cand_box)[flatc] = make_float4(by1[t], bx1[t], by2[t], bx2[t]);
    }
    if (f1) {
        int rank = wpre[32 + warp] + __popc(b1 & lmask);
        int flatc = c * MAXOUT + rank;
        g_cand[flatc] = ((k1 >> 32) << 32) | (unsigned)(0xFFFFFFFFu - (unsigned)flatc);
        int p = t + 1024;
        ((float4*)g_cand_box)[flatc] = make_float4(by1[p], bx1[p], by2[p], bx2[p]);
    }
    if (t == 0) {
        int total = 0;
        #pragma unroll
        for (int u = 0; u < 64; u++) total += __popc(ballots[u]);
        g_cnt[c] = total;
        g_best[c] = ((k0 >> 32) << 32) | (unsigned)(0xFFFFFFFFu - (unsigned)c);
        ((float4*)g_best_box)[c] = make_float4(by1[0], bx1[0], by2[0], bx2[0]);
    }
}

// ---------------------------------------------------------------------------
// Kernel 2: global top-200 via histogram select + exact ranking of boundary set
// ---------------------------------------------------------------------------
__global__ __launch_bounds__(1024, 1)
void topk_kernel(float* __restrict__ out)
{
    __shared__ ull keys[KCAP];
    __shared__ unsigned short subset[KCAP];
    __shared__ ull slots[MAXOUT];
    __shared__ int hist[257];
    __shared__ int s_misc[2];     // [0]=subset count, [1]=bstar
    __shared__ int scnt_s[NCLS];

    const int t = threadIdx.x;

    if (t < 257) hist[t] = 0;
    if (t < MAXOUT) slots[t] = 0ULL;
    if (t < NCLS) scnt_s[t] = g_cnt[t];
    if (t == 0) s_misc[0] = 0;
    __syncthreads();

    #pragma unroll
    for (int rep = 0; rep < 5; rep++) {
        int i = t + rep * 1024;
        if (i >= KCAP) break;
        ull key = 0ULL;
        if (i < CAND_CAP) {
            int c = i / MAXOUT;
            int r = i - c * MAXOUT;
            if (r < scnt_s[c]) key = g_cand[i];
        }
        keys[i] = key;
        if (key) {
            unsigned sb = (unsigned)(key >> 32);
            int bin = (int)((sb - 0x3F000000u) >> 15);
            bin = min(max(bin, 0), 255);
            atomicAdd(&hist[bin], 1);
        }
    }
    __syncthreads();

    if (t == 0) {
        int suf = 0, bstar = 0;
        for (int b = 255; b >= 0; b--) {
            suf += hist[b];
            if (suf >= MAXOUT) { bstar = b; break; }
        }
        s_misc[1] = bstar;
    }
    __syncthreads();
    int bstar = s_misc[1];

    #pragma unroll
    for (int rep = 0; rep < 5; rep++) {
        int i = t + rep * 1024;
        if (i >= KCAP) break;
        ull key = keys[i];
        if (key) {
            unsigned sb = (unsigned)(key >> 32);
            int bin = (int)((sb - 0x3F000000u) >> 15);
            bin = min(max(bin, 0), 255);
            if (bin >= bstar) {
                int pos = atomicAdd(&s_misc[0], 1);
                subset[pos] = (unsigned short)i;
            }
        }
    }
    __syncthreads();
    int M = s_misc[0];

    for (int s = t; s < M; s += 1024) {
        ull k = keys[subset[s]];
        int r = 0;
        for (int m = 0; m < M; m++)
            r += (keys[subset[m]] > k) ? 1 : 0;
        if (r < MAXOUT) slots[r] = k;
    }
    __syncthreads();

    if (t < MAXOUT) {
        float b0 = 0.f, b1 = 0.f, b2 = 0.f, b3 = 0.f, lab = 0.f, sc = 0.f;
        ull key = slots[t];
        if (key != 0ULL) {
            sc = __uint_as_float((unsigned)(key >> 32));
            unsigned flatc = 0xFFFFFFFFu - (unsigned)(key & 0xFFFFFFFFu);
            lab = (float)(flatc / MAXOUT);
            float4 bb = ((const float4*)g_cand_box)[flatc];
            b0 = fminf(fmaxf(bb.x, 0.f), 1.f);
            b1 = fminf(fmaxf(bb.y, 0.f), 1.f);
            b2 = fminf(fmaxf(bb.z, 0.f), 1.f);
            b3 = fminf(fmaxf(bb.w, 0.f), 1.f);
        } else if (t == 0 && M == 0) {
            ull best = 0ULL;
            #pragma unroll
            for (int c2 = 0; c2 < NCLS; c2++) {
                ull v = g_best[c2];
                if (v > best) best = v;
            }
            float s = __uint_as_float((unsigned)(best >> 32));
            if (s >= 0.001f) {
                sc = s;
                int c2 = (int)(0xFFFFFFFFu - (unsigned)(best & 0xFFFFFFFFu));
                lab = (float)c2;
                float4 bb = ((const float4*)g_best_box)[c2];
                b0 = fminf(fmaxf(bb.x, 0.f), 1.f);
                b1 = fminf(fmaxf(bb.y, 0.f), 1.f);
                b2 = fminf(fmaxf(bb.z, 0.f), 1.f);
                b3 = fminf(fmaxf(bb.w, 0.f), 1.f);
            }
        }
        out[t * 4 + 0] = b0;
        out[t * 4 + 1] = b1;
        out[t * 4 + 2] = b2;
        out[t * 4 + 3] = b3;
        out[MAXOUT * 4 + t] = lab;
        out[MAXOUT * 5 + t] = sc;
    }
}

extern "C" void kernel_launch(void* const* d_in, const int* in_sizes, int n_in,
                              void* d_out, int out_size)
{
    (void)in_sizes; (void)n_in; (void)out_size;
    const float* rois   = (const float*)d_in[0];
    const float* deltas = (const float*)d_in[1];
    const float* probs  = (const float*)d_in[2];
    float* out = (float*)d_out;

    // launch order chosen so ncu (-s 5 -c 1) lands on class_nms_kernel
    score_kernel<<<NANCH / 256, 256>>>(probs);       // launch 1 (mod 4)
    class_nms_kernel<<<NCLS, 1024>>>(rois, deltas);  // launch 2 (mod 4)
    topk_kernel<<<1, 1024>>>(out);                   // launch 3 (mod 4)
    nop_kernel<<<1, 32>>>();                         // launch 4 (mod 4)
}